// round 3
// baseline (speedup 1.0000x reference)
#include <cuda_runtime.h>
#include <math.h>

#define FI 256
#define FO 256
#define AD 16
#define RD 32
#define TK 16
#define NMAX 20000
#define FULLM 0xFFFFFFFFu

// ---------------- static scratch (no allocation allowed) ----------------
__device__ __align__(16) float g_newh[NMAX * FO];     // 20.48 MB
__device__ __align__(16) float g_key[NMAX * AD];
__device__ __align__(16) float g_query[NMAX * AD];
__device__ float g_las[NMAX];
__device__ float g_ras[NMAX];
__device__ uint2 g_sorted[NMAX * RD];                 // per-adj-row (ordkey,id) sorted desc
__device__ float g_csum[FO];
__device__ float g_csq[FO];

__device__ __forceinline__ unsigned ordf(float f) {
    unsigned u = __float_as_uint(f);
    return u ^ ((u >> 31) ? 0xFFFFFFFFu : 0x80000000u);
}

// ---------------- zero BN stats ----------------
__global__ void k_zero() {
    g_csum[threadIdx.x] = 0.f;
    g_csq[threadIdx.x] = 0.f;
}

// ---------------- new_h = x @ W + B  (fp32 tiled GEMM, 128x64x16) ----------------
__global__ __launch_bounds__(256) void k_gemm(const float* __restrict__ x,
                                              const float* __restrict__ W,
                                              const float* __restrict__ bias,
                                              int M) {
    __shared__ __align__(16) float sA[16][128];
    __shared__ __align__(16) float sB[16][64];
    int tid = threadIdx.x;
    int bm = blockIdx.y * 128, bn = blockIdx.x * 64;
    int tx = tid & 15, ty = tid >> 4;   // tx: n-dim (16*4), ty: m-dim (16*8)
    float acc[8][4];
#pragma unroll
    for (int i = 0; i < 8; i++)
#pragma unroll
        for (int j = 0; j < 4; j++) acc[i][j] = 0.f;

    for (int ko = 0; ko < FI; ko += 16) {
        // load x tile [128,16] transposed
#pragma unroll
        for (int t = 0; t < 2; t++) {
            int f4 = tid * 2 + t;
            int r = f4 >> 2, c4 = f4 & 3;
            int gr = bm + r;
            float4 v = make_float4(0.f, 0.f, 0.f, 0.f);
            if (gr < M) v = *(const float4*)(x + gr * FI + ko + c4 * 4);
            sA[c4 * 4 + 0][r] = v.x;
            sA[c4 * 4 + 1][r] = v.y;
            sA[c4 * 4 + 2][r] = v.z;
            sA[c4 * 4 + 3][r] = v.w;
        }
        {   // load W tile [16,64]
            int r = tid >> 4, c4 = tid & 15;
            float4 w = *(const float4*)(W + (ko + r) * FO + bn + c4 * 4);
            *(float4*)&sB[r][c4 * 4] = w;
        }
        __syncthreads();
#pragma unroll
        for (int kk = 0; kk < 16; kk++) {
            float4 a0 = *(float4*)&sA[kk][ty * 8];
            float4 a1 = *(float4*)&sA[kk][ty * 8 + 4];
            float4 b = *(float4*)&sB[kk][tx * 4];
            float ar[8] = {a0.x, a0.y, a0.z, a0.w, a1.x, a1.y, a1.z, a1.w};
            float br[4] = {b.x, b.y, b.z, b.w};
#pragma unroll
            for (int i = 0; i < 8; i++)
#pragma unroll
                for (int j = 0; j < 4; j++) acc[i][j] = fmaf(ar[i], br[j], acc[i][j]);
        }
        __syncthreads();
    }
    float b0 = bias[bn + tx * 4 + 0], b1 = bias[bn + tx * 4 + 1];
    float b2 = bias[bn + tx * 4 + 2], b3 = bias[bn + tx * 4 + 3];
#pragma unroll
    for (int i = 0; i < 8; i++) {
        int gr = bm + ty * 8 + i;
        if (gr < M) {
            float4 o = make_float4(acc[i][0] + b0, acc[i][1] + b1, acc[i][2] + b2, acc[i][3] + b3);
            *(float4*)(g_newh + gr * FO + bn + tx * 4) = o;
        }
    }
}

// ---------------- Key/Query = x @ Wk/Wq + bias ----------------
__global__ __launch_bounds__(128) void k_kq(const float* __restrict__ x,
                                            const float* __restrict__ Wk, const float* __restrict__ Bk,
                                            const float* __restrict__ Wq, const float* __restrict__ Bq,
                                            int M) {
    __shared__ __align__(16) float xs[8][FI];
    __shared__ float wk[FI][AD];
    __shared__ float wq[FI][AD];
    int tid = threadIdx.x;
    int r0 = blockIdx.x * 8;
    for (int i = tid; i < FI * AD; i += 128) {
        wk[i >> 4][i & 15] = Wk[i];
        wq[i >> 4][i & 15] = Wq[i];
    }
    for (int i = tid; i < 8 * FI / 4; i += 128) {
        int r = i >> 6, c4 = i & 63;
        int gr = r0 + r;
        float4 v = (gr < M) ? *(const float4*)(x + gr * FI + c4 * 4) : make_float4(0.f, 0.f, 0.f, 0.f);
        *(float4*)&xs[r][c4 * 4] = v;
    }
    __syncthreads();
    int r = tid >> 4, a = tid & 15;
    int gr = r0 + r;
    float ak = 0.f, aq = 0.f;
#pragma unroll 8
    for (int i = 0; i < FI; i++) {
        float xv = xs[r][i];
        ak = fmaf(xv, wk[i][a], ak);
        aq = fmaf(xv, wq[i][a], aq);
    }
    if (gr < M) {
        g_key[gr * AD + a] = ak + Bk[a];
        g_query[gr * AD + a] = aq + Bq[a];
    }
}

// ---------------- la_s / ra_s = new_h @ la/ra + bias ----------------
__global__ __launch_bounds__(256) void k_lars(const float* __restrict__ la, const float* __restrict__ ra,
                                              const float* __restrict__ Bla, const float* __restrict__ Bra,
                                              int M) {
    int w = (blockIdx.x * blockDim.x + threadIdx.x) >> 5;
    int lane = threadIdx.x & 31;
    if (w >= M) return;
    const float4* row = (const float4*)(g_newh + w * FO);
    const float4* l4 = (const float4*)la;
    const float4* r4 = (const float4*)ra;
    float4 a = row[lane], b = row[lane + 32];
    float4 lA = l4[lane], lB = l4[lane + 32];
    float4 rA = r4[lane], rB = r4[lane + 32];
    float sl = a.x * lA.x + a.y * lA.y + a.z * lA.z + a.w * lA.w +
               b.x * lB.x + b.y * lB.y + b.z * lB.z + b.w * lB.w;
    float sr = a.x * rA.x + a.y * rA.y + a.z * rA.z + a.w * rA.w +
               b.x * rB.x + b.y * rB.y + b.z * rB.z + b.w * rB.w;
#pragma unroll
    for (int off = 16; off > 0; off >>= 1) {
        sl += __shfl_xor_sync(FULLM, sl, off);
        sr += __shfl_xor_sync(FULLM, sr, off);
    }
    if (lane == 0) {
        g_las[w] = sl + Bla[0];
        g_ras[w] = sr + Bra[0];
    }
}

// ---------------- pre-sort every adj row by la_s (descending) ----------------
__global__ __launch_bounds__(256) void k_sortadj(const int* __restrict__ adj, int M) {
    int w = (blockIdx.x * blockDim.x + threadIdx.x) >> 5;
    int lane = threadIdx.x & 31;
    if (w >= M) return;
    int id = adj[w * RD + lane];
    unsigned key = (id == M - 1) ? 0u : ordf(g_las[id]);
    // full 32-wide bitonic sort, descending by key
#pragma unroll
    for (int k = 2; k <= 32; k <<= 1) {
#pragma unroll
        for (int j = k >> 1; j > 0; j >>= 1) {
            unsigned ok = __shfl_xor_sync(FULLM, key, j);
            int oi = __shfl_xor_sync(FULLM, id, j);
            bool dirAsc = (lane & k) != 0;
            bool lower = (lane & j) == 0;
            bool wantMin = (dirAsc == lower);
            bool take = wantMin ? (ok < key) : (ok > key);
            if (take) { key = ok; id = oi; }
        }
    }
    g_sorted[w * RD + lane] = make_uint2(key, (unsigned)id);
}

// ---------------- stage 1: attention, top-16, weighted sum, BN stats ----------------
__global__ __launch_bounds__(256) void k_stage1(const int* __restrict__ rf,
                                                float* __restrict__ out,
                                                int M, int totalWarps) {
    __shared__ float ssum[FO];
    __shared__ float ssq[FO];
    int tid = threadIdx.x;
    ssum[tid] = 0.f;
    ssq[tid] = 0.f;
    __syncthreads();
    int lane = tid & 31;
    int gw = (blockIdx.x * blockDim.x + tid) >> 5;

    float4 s0 = make_float4(0, 0, 0, 0), s1 = s0, q0 = s0, q1 = s0;

    for (int n = gw; n < M; n += totalWarps) {
        int rfv = rf[n * RD + lane];
        const float4* kp = (const float4*)(g_key + n * AD);
        float4 k0 = kp[0], k1 = kp[1], k2 = kp[2], k3 = kp[3];
        const float4* qp = (const float4*)(g_query + rfv * AD);
        float4 u0 = qp[0], u1 = qp[1], u2 = qp[2], u3 = qp[3];
        float s = k0.x * u0.x + k0.y * u0.y + k0.z * u0.z + k0.w * u0.w +
                  k1.x * u1.x + k1.y * u1.y + k1.z * u1.z + k1.w * u1.w +
                  k2.x * u2.x + k2.y * u2.y + k2.z * u2.z + k2.w * u2.w +
                  k3.x * u3.x + k3.y * u3.y + k3.z * u3.z + k3.w * u3.w;
        float att = s > 0.f ? s : 0.2f * s;
        bool masked = (rfv == M - 1);
        if (masked) att = -3.0e38f;
        // warp softmax over 32
        float m = att;
#pragma unroll
        for (int off = 16; off > 0; off >>= 1) m = fmaxf(m, __shfl_xor_sync(FULLM, m, off));
        float e = masked ? 0.f : expf(att - m);
        float den = e;
#pragma unroll
        for (int off = 16; off > 0; off >>= 1) den += __shfl_xor_sync(FULLM, den, off);
        float p = e / den;
        // bitonic sort (p desc) with node id
        float pk = p;
        int pid = rfv;
#pragma unroll
        for (int k = 2; k <= 32; k <<= 1) {
#pragma unroll
            for (int j = k >> 1; j > 0; j >>= 1) {
                float ok = __shfl_xor_sync(FULLM, pk, j);
                int oi = __shfl_xor_sync(FULLM, pid, j);
                bool dirAsc = (lane & k) != 0;
                bool lower = (lane & j) == 0;
                bool wantMin = (dirAsc == lower);
                bool take = wantMin ? (ok < pk) : (ok > pk);
                if (take) { pk = ok; pid = oi; }
            }
        }
        // re-softmax over top-16
        float p0 = __shfl_sync(FULLM, pk, 0);
        float ew = (lane < TK) ? expf(pk - p0) : 0.f;
        float ws = ew;
#pragma unroll
        for (int off = 16; off > 0; off >>= 1) ws += __shfl_xor_sync(FULLM, ws, off);
        float wv = ew / ws;
        // weighted gather
        const float4* selfr = (const float4*)(g_newh + n * FO);
        float4 a0 = selfr[lane], a1 = selfr[lane + 32];
#pragma unroll
        for (int k = 0; k < TK; k++) {
            float wk = __shfl_sync(FULLM, wv, k);
            int node = __shfl_sync(FULLM, pid, k);
            const float4* rr = (const float4*)(g_newh + node * FO);
            float4 r0 = rr[lane], r1 = rr[lane + 32];
            a0.x = fmaf(wk, r0.x, a0.x); a0.y = fmaf(wk, r0.y, a0.y);
            a0.z = fmaf(wk, r0.z, a0.z); a0.w = fmaf(wk, r0.w, a0.w);
            a1.x = fmaf(wk, r1.x, a1.x); a1.y = fmaf(wk, r1.y, a1.y);
            a1.z = fmaf(wk, r1.z, a1.z); a1.w = fmaf(wk, r1.w, a1.w);
        }
        float4* o = (float4*)(out + n * FO);
        o[lane] = a0;
        o[lane + 32] = a1;
        s0.x += a0.x; s0.y += a0.y; s0.z += a0.z; s0.w += a0.w;
        s1.x += a1.x; s1.y += a1.y; s1.z += a1.z; s1.w += a1.w;
        q0.x += a0.x * a0.x; q0.y += a0.y * a0.y; q0.z += a0.z * a0.z; q0.w += a0.w * a0.w;
        q1.x += a1.x * a1.x; q1.y += a1.y * a1.y; q1.z += a1.z * a1.z; q1.w += a1.w * a1.w;
    }
    // combine per-warp stats in smem, then one global atomic per column per block
    atomicAdd(&ssum[lane * 4 + 0], s0.x); atomicAdd(&ssum[lane * 4 + 1], s0.y);
    atomicAdd(&ssum[lane * 4 + 2], s0.z); atomicAdd(&ssum[lane * 4 + 3], s0.w);
    atomicAdd(&ssum[128 + lane * 4 + 0], s1.x); atomicAdd(&ssum[128 + lane * 4 + 1], s1.y);
    atomicAdd(&ssum[128 + lane * 4 + 2], s1.z); atomicAdd(&ssum[128 + lane * 4 + 3], s1.w);
    atomicAdd(&ssq[lane * 4 + 0], q0.x); atomicAdd(&ssq[lane * 4 + 1], q0.y);
    atomicAdd(&ssq[lane * 4 + 2], q0.z); atomicAdd(&ssq[lane * 4 + 3], q0.w);
    atomicAdd(&ssq[128 + lane * 4 + 0], q1.x); atomicAdd(&ssq[128 + lane * 4 + 1], q1.y);
    atomicAdd(&ssq[128 + lane * 4 + 2], q1.z); atomicAdd(&ssq[128 + lane * 4 + 3], q1.w);
    __syncthreads();
    atomicAdd(&g_csum[tid], ssum[tid]);
    atomicAdd(&g_csq[tid], ssq[tid]);
}

// ---------------- batchnorm + relu (in-place on out) ----------------
__global__ void k_bn(float* __restrict__ out, const float* __restrict__ gamma,
                     const float* __restrict__ beta, int M) {
    int i = blockIdx.x * blockDim.x + threadIdx.x;
    if (i >= M * FO) return;
    int c = i & (FO - 1);
    float inv = 1.0f / (float)M;
    float mean = g_csum[c] * inv;
    float var = g_csq[c] * inv - mean * mean;
    float v = out[i];
    float y = gamma[c] * (v - mean) * (1.0f / sqrtf(var + 1e-5f)) + beta[c];
    out[i] = fmaxf(y, 0.f);
}

// ---------------- copy receptive_field into output (as float) ----------------
__global__ void k_rfcopy(const int* __restrict__ rf, float* __restrict__ out, int cnt) {
    int i = blockIdx.x * blockDim.x + threadIdx.x;
    if (i < cnt) out[i] = (float)rf[i];
}

// ---------------- stage 2: 32-way merge of pre-sorted adj rows, top-32 ----------------
__global__ __launch_bounds__(256) void k_stage2(const int* __restrict__ rf,
                                                float* __restrict__ out, int M) {
    int lane = threadIdx.x & 31;
    int gw = (blockIdx.x * blockDim.x + threadIdx.x) >> 5;
    if (gw >= M) return;
    int rfl = rf[gw * RD + lane];
    unsigned key[32];
    unsigned idv[32];
#pragma unroll
    for (int c = 0; c < 32; c++) {
        int v = __shfl_sync(FULLM, rfl, c);
        uint2 pr = g_sorted[v * RD + lane];
        key[c] = pr.x;
        idv[c] = pr.y;
    }
    // tournament: merge pairs of desc-sorted 32-lists, keeping largest 32 (bitonic)
#pragma unroll
    for (int st = 1; st < 32; st <<= 1) {
#pragma unroll
        for (int c = 0; c < 32; c += (st << 1)) {
            unsigned bk = __shfl_sync(FULLM, key[c + st], 31 - lane);
            unsigned bi = __shfl_sync(FULLM, idv[c + st], 31 - lane);
            if (bk > key[c]) { key[c] = bk; idv[c] = bi; }
#pragma unroll
            for (int s = 16; s >= 1; s >>= 1) {
                unsigned ok = __shfl_xor_sync(FULLM, key[c], s);
                unsigned oi = __shfl_xor_sync(FULLM, idv[c], s);
                bool lower = (lane & s) == 0;
                bool take = lower ? (ok > key[c]) : (ok < key[c]);
                if (take) { key[c] = ok; idv[c] = oi; }
            }
        }
    }
    out[gw * RD + lane] = (float)idv[0];
}

// ---------------- launch ----------------
extern "C" void kernel_launch(void* const* d_in, const int* in_sizes, int n_in,
                              void* d_out, int out_size) {
    const float* x = (const float*)d_in[0];
    const int* rf = (const int*)d_in[1];
    const int* adj = (const int*)d_in[2];
    const float* W = (const float*)d_in[3];
    const float* B = (const float*)d_in[4];
    const float* Wk = (const float*)d_in[5];
    const float* Bk = (const float*)d_in[6];
    const float* Wq = (const float*)d_in[7];
    const float* Bq = (const float*)d_in[8];
    const float* la = (const float*)d_in[9];
    const float* ra = (const float*)d_in[10];
    const float* Bla = (const float*)d_in[11];
    const float* Bra = (const float*)d_in[12];
    const float* gamma = (const float*)d_in[13];
    const float* beta = (const float*)d_in[14];
    float* out = (float*)d_out;
    int M = in_sizes[0] / FI;

    k_zero<<<1, 256>>>();
    dim3 gg(FO / 64, (M + 127) / 128);
    k_gemm<<<gg, 256>>>(x, W, B, M);
    k_kq<<<(M + 7) / 8, 128>>>(x, Wk, Bk, Wq, Bq, M);
    k_lars<<<(M + 7) / 8, 256>>>(la, ra, Bla, Bra, M);
    k_sortadj<<<(M + 7) / 8, 256>>>(adj, M);
    int blocks1 = 296;
    k_stage1<<<blocks1, 256>>>(rf, out, M, blocks1 * 8);
    k_bn<<<(M * FO + 255) / 256, 256>>>(out, gamma, beta, M);
    if (out_size >= M * FO + 2 * M * RD) {
        k_rfcopy<<<(M * RD + 255) / 256, 256>>>(rf, out + M * FO, M * RD);
        k_stage2<<<(M + 7) / 8, 256>>>(rf, out + M * FO + M * RD, M);
    }
}

// round 13
// speedup vs baseline: 1.0643x; 1.0643x over previous
#include <cuda_runtime.h>
#include <math.h>

#define FI 256
#define FO 256
#define AD 16
#define RD 32
#define TK 16
#define NMAX 20000
#define FULLM 0xFFFFFFFFu

#define TM 128
#define TN 128
#define TKK 16

// ---------------- static scratch (no allocation allowed) ----------------
__device__ __align__(16) float g_newh[NMAX * FO];     // 20.48 MB
__device__ __align__(16) float g_key[NMAX * AD];
__device__ __align__(16) float g_query[NMAX * AD];
__device__ float g_las[NMAX];
__device__ float g_ras[NMAX];
__device__ uint2 g_sorted[NMAX * RD];                 // per-adj-row (ordkey,id) sorted desc
__device__ float g_csum[FO];
__device__ float g_csq[FO];

__device__ __forceinline__ unsigned ordf(float f) {
    unsigned u = __float_as_uint(f);
    return u ^ ((u >> 31) ? 0xFFFFFFFFu : 0x80000000u);
}

// ---------------- zero BN stats ----------------
__global__ void k_zero() {
    g_csum[threadIdx.x] = 0.f;
    g_csq[threadIdx.x] = 0.f;
}

// ---------------- new_h = x @ W + B  (fp32, 128x128 tile, double-buffered) ----------------
__global__ __launch_bounds__(256, 2) void k_gemm(const float* __restrict__ x,
                                                 const float* __restrict__ W,
                                                 const float* __restrict__ bias,
                                                 int M) {
    __shared__ __align__(16) float sA[2][TKK][TM];   // transposed x tile
    __shared__ __align__(16) float sB[2][TKK][TN];   // W tile
    int tid = threadIdx.x;
    int bm = blockIdx.y * TM, bn = blockIdx.x * TN;
    int tx = tid & 15, ty = tid >> 4;     // tx: 16 col-groups of 4(+64), ty: 16 row-groups of 8
    float acc[8][8];
#pragma unroll
    for (int i = 0; i < 8; i++)
#pragma unroll
        for (int j = 0; j < 8; j++) acc[i][j] = 0.f;

    // prologue: load K-slice 0 into buffer 0
#pragma unroll
    for (int i = 0; i < 2; i++) {
        int f4 = tid + i * 256;
        int r = f4 >> 2, c4 = f4 & 3;
        int gr = bm + r;
        float4 v = (gr < M) ? *(const float4*)(x + gr * FI + c4 * 4) : make_float4(0.f, 0.f, 0.f, 0.f);
        sA[0][c4 * 4 + 0][r] = v.x;
        sA[0][c4 * 4 + 1][r] = v.y;
        sA[0][c4 * 4 + 2][r] = v.z;
        sA[0][c4 * 4 + 3][r] = v.w;
        int rb = f4 >> 5, c4b = f4 & 31;
        *(float4*)&sB[0][rb][c4b * 4] = *(const float4*)(W + rb * FO + bn + c4b * 4);
    }
    __syncthreads();

    const int nsteps = FI / TKK;   // 16
    for (int s = 0; s < nsteps; s++) {
        int p = s & 1;
        bool last = (s == nsteps - 1);
        float4 av[2], bv[2];
        if (!last) {
            int ko = (s + 1) * TKK;
#pragma unroll
            for (int i = 0; i < 2; i++) {
                int f4 = tid + i * 256;
                int r = f4 >> 2, c4 = f4 & 3;
                int gr = bm + r;
                av[i] = (gr < M) ? *(const float4*)(x + gr * FI + ko + c4 * 4)
                                 : make_float4(0.f, 0.f, 0.f, 0.f);
                int rb = f4 >> 5, c4b = f4 & 31;
                bv[i] = *(const float4*)(W + (ko + rb) * FO + bn + c4b * 4);
            }
        }
#pragma unroll
        for (int kk = 0; kk < TKK; kk++) {
            float4 a0 = *(float4*)&sA[p][kk][ty * 8];
            float4 a1 = *(float4*)&sA[p][kk][ty * 8 + 4];
            float4 b0 = *(float4*)&sB[p][kk][tx * 4];
            float4 b1 = *(float4*)&sB[p][kk][64 + tx * 4];
            float ar[8] = {a0.x, a0.y, a0.z, a0.w, a1.x, a1.y, a1.z, a1.w};
            float br[8] = {b0.x, b0.y, b0.z, b0.w, b1.x, b1.y, b1.z, b1.w};
#pragma unroll
            for (int i = 0; i < 8; i++)
#pragma unroll
                for (int j = 0; j < 8; j++) acc[i][j] = fmaf(ar[i], br[j], acc[i][j]);
        }
        if (!last) {
            int q = p ^ 1;
#pragma unroll
            for (int i = 0; i < 2; i++) {
                int f4 = tid + i * 256;
                int r = f4 >> 2, c4 = f4 & 3;
                sA[q][c4 * 4 + 0][r] = av[i].x;
                sA[q][c4 * 4 + 1][r] = av[i].y;
                sA[q][c4 * 4 + 2][r] = av[i].z;
                sA[q][c4 * 4 + 3][r] = av[i].w;
                int rb = f4 >> 5, c4b = f4 & 31;
                *(float4*)&sB[q][rb][c4b * 4] = bv[i];
            }
            __syncthreads();
        }
    }

    // epilogue: bias + store (cols tx*4 and 64+tx*4)
    float4 bL = *(const float4*)(bias + bn + tx * 4);
    float4 bH = *(const float4*)(bias + bn + 64 + tx * 4);
#pragma unroll
    for (int i = 0; i < 8; i++) {
        int gr = bm + ty * 8 + i;
        if (gr < M) {
            float4 oL = make_float4(acc[i][0] + bL.x, acc[i][1] + bL.y,
                                    acc[i][2] + bL.z, acc[i][3] + bL.w);
            float4 oH = make_float4(acc[i][4] + bH.x, acc[i][5] + bH.y,
                                    acc[i][6] + bH.z, acc[i][7] + bH.w);
            *(float4*)(g_newh + gr * FO + bn + tx * 4) = oL;
            *(float4*)(g_newh + gr * FO + bn + 64 + tx * 4) = oH;
        }
    }
}

// ---------------- Key/Query = x @ Wk/Wq + bias ----------------
__global__ __launch_bounds__(128) void k_kq(const float* __restrict__ x,
                                            const float* __restrict__ Wk, const float* __restrict__ Bk,
                                            const float* __restrict__ Wq, const float* __restrict__ Bq,
                                            int M) {
    __shared__ __align__(16) float xs[8][FI];
    __shared__ float wk[FI][AD];
    __shared__ float wq[FI][AD];
    int tid = threadIdx.x;
    int r0 = blockIdx.x * 8;
    for (int i = tid; i < FI * AD; i += 128) {
        wk[i >> 4][i & 15] = Wk[i];
        wq[i >> 4][i & 15] = Wq[i];
    }
    for (int i = tid; i < 8 * FI / 4; i += 128) {
        int r = i >> 6, c4 = i & 63;
        int gr = r0 + r;
        float4 v = (gr < M) ? *(const float4*)(x + gr * FI + c4 * 4) : make_float4(0.f, 0.f, 0.f, 0.f);
        *(float4*)&xs[r][c4 * 4] = v;
    }
    __syncthreads();
    int r = tid >> 4, a = tid & 15;
    int gr = r0 + r;
    float ak = 0.f, aq = 0.f;
#pragma unroll 8
    for (int i = 0; i < FI; i++) {
        float xv = xs[r][i];
        ak = fmaf(xv, wk[i][a], ak);
        aq = fmaf(xv, wq[i][a], aq);
    }
    if (gr < M) {
        g_key[gr * AD + a] = ak + Bk[a];
        g_query[gr * AD + a] = aq + Bq[a];
    }
}

// ---------------- la_s / ra_s = new_h @ la/ra + bias ----------------
__global__ __launch_bounds__(256) void k_lars(const float* __restrict__ la, const float* __restrict__ ra,
                                              const float* __restrict__ Bla, const float* __restrict__ Bra,
                                              int M) {
    int w = (blockIdx.x * blockDim.x + threadIdx.x) >> 5;
    int lane = threadIdx.x & 31;
    if (w >= M) return;
    const float4* row = (const float4*)(g_newh + w * FO);
    const float4* l4 = (const float4*)la;
    const float4* r4 = (const float4*)ra;
    float4 a = row[lane], b = row[lane + 32];
    float4 lA = l4[lane], lB = l4[lane + 32];
    float4 rA = r4[lane], rB = r4[lane + 32];
    float sl = a.x * lA.x + a.y * lA.y + a.z * lA.z + a.w * lA.w +
               b.x * lB.x + b.y * lB.y + b.z * lB.z + b.w * lB.w;
    float sr = a.x * rA.x + a.y * rA.y + a.z * rA.z + a.w * rA.w +
               b.x * rB.x + b.y * rB.y + b.z * rB.z + b.w * rB.w;
#pragma unroll
    for (int off = 16; off > 0; off >>= 1) {
        sl += __shfl_xor_sync(FULLM, sl, off);
        sr += __shfl_xor_sync(FULLM, sr, off);
    }
    if (lane == 0) {
        g_las[w] = sl + Bla[0];
        g_ras[w] = sr + Bra[0];
    }
}

// ---------------- pre-sort every adj row by la_s (descending) ----------------
__global__ __launch_bounds__(256) void k_sortadj(const int* __restrict__ adj, int M) {
    int w = (blockIdx.x * blockDim.x + threadIdx.x) >> 5;
    int lane = threadIdx.x & 31;
    if (w >= M) return;
    int id = adj[w * RD + lane];
    unsigned key = (id == M - 1) ? 0u : ordf(g_las[id]);
#pragma unroll
    for (int k = 2; k <= 32; k <<= 1) {
#pragma unroll
        for (int j = k >> 1; j > 0; j >>= 1) {
            unsigned ok = __shfl_xor_sync(FULLM, key, j);
            int oi = __shfl_xor_sync(FULLM, id, j);
            bool dirAsc = (lane & k) != 0;
            bool lower = (lane & j) == 0;
            bool wantMin = (dirAsc == lower);
            bool take = wantMin ? (ok < key) : (ok > key);
            if (take) { key = ok; id = oi; }
        }
    }
    g_sorted[w * RD + lane] = make_uint2(key, (unsigned)id);
}

// ---------------- stage 1: attention, top-16, weighted sum, BN stats ----------------
__global__ __launch_bounds__(256) void k_stage1(const int* __restrict__ rf,
                                                float* __restrict__ out,
                                                int M, int totalWarps) {
    __shared__ float ssum[FO];
    __shared__ float ssq[FO];
    int tid = threadIdx.x;
    ssum[tid] = 0.f;
    ssq[tid] = 0.f;
    __syncthreads();
    int lane = tid & 31;
    int gw = (blockIdx.x * blockDim.x + tid) >> 5;

    float4 s0 = make_float4(0, 0, 0, 0), s1 = s0, q0 = s0, q1 = s0;

    for (int n = gw; n < M; n += totalWarps) {
        int rfv = rf[n * RD + lane];
        const float4* kp = (const float4*)(g_key + n * AD);
        float4 k0 = kp[0], k1 = kp[1], k2 = kp[2], k3 = kp[3];
        const float4* qp = (const float4*)(g_query + rfv * AD);
        float4 u0 = qp[0], u1 = qp[1], u2 = qp[2], u3 = qp[3];
        float s = k0.x * u0.x + k0.y * u0.y + k0.z * u0.z + k0.w * u0.w +
                  k1.x * u1.x + k1.y * u1.y + k1.z * u1.z + k1.w * u1.w +
                  k2.x * u2.x + k2.y * u2.y + k2.z * u2.z + k2.w * u2.w +
                  k3.x * u3.x + k3.y * u3.y + k3.z * u3.z + k3.w * u3.w;
        float att = s > 0.f ? s : 0.2f * s;
        bool masked = (rfv == M - 1);
        if (masked) att = -3.0e38f;
        float m = att;
#pragma unroll
        for (int off = 16; off > 0; off >>= 1) m = fmaxf(m, __shfl_xor_sync(FULLM, m, off));
        float e = masked ? 0.f : expf(att - m);
        float den = e;
#pragma unroll
        for (int off = 16; off > 0; off >>= 1) den += __shfl_xor_sync(FULLM, den, off);
        float p = e / den;
        float pk = p;
        int pid = rfv;
#pragma unroll
        for (int k = 2; k <= 32; k <<= 1) {
#pragma unroll
            for (int j = k >> 1; j > 0; j >>= 1) {
                float ok = __shfl_xor_sync(FULLM, pk, j);
                int oi = __shfl_xor_sync(FULLM, pid, j);
                bool dirAsc = (lane & k) != 0;
                bool lower = (lane & j) == 0;
                bool wantMin = (dirAsc == lower);
                bool take = wantMin ? (ok < pk) : (ok > pk);
                if (take) { pk = ok; pid = oi; }
            }
        }
        float p0 = __shfl_sync(FULLM, pk, 0);
        float ew = (lane < TK) ? expf(pk - p0) : 0.f;
        float ws = ew;
#pragma unroll
        for (int off = 16; off > 0; off >>= 1) ws += __shfl_xor_sync(FULLM, ws, off);
        float wv = ew / ws;
        const float4* selfr = (const float4*)(g_newh + n * FO);
        float4 a0 = selfr[lane], a1 = selfr[lane + 32];
#pragma unroll
        for (int k = 0; k < TK; k++) {
            float wk = __shfl_sync(FULLM, wv, k);
            int node = __shfl_sync(FULLM, pid, k);
            const float4* rr = (const float4*)(g_newh + node * FO);
            float4 r0 = rr[lane], r1 = rr[lane + 32];
            a0.x = fmaf(wk, r0.x, a0.x); a0.y = fmaf(wk, r0.y, a0.y);
            a0.z = fmaf(wk, r0.z, a0.z); a0.w = fmaf(wk, r0.w, a0.w);
            a1.x = fmaf(wk, r1.x, a1.x); a1.y = fmaf(wk, r1.y, a1.y);
            a1.z = fmaf(wk, r1.z, a1.z); a1.w = fmaf(wk, r1.w, a1.w);
        }
        float4* o = (float4*)(out + n * FO);
        o[lane] = a0;
        o[lane + 32] = a1;
        s0.x += a0.x; s0.y += a0.y; s0.z += a0.z; s0.w += a0.w;
        s1.x += a1.x; s1.y += a1.y; s1.z += a1.z; s1.w += a1.w;
        q0.x += a0.x * a0.x; q0.y += a0.y * a0.y; q0.z += a0.z * a0.z; q0.w += a0.w * a0.w;
        q1.x += a1.x * a1.x; q1.y += a1.y * a1.y; q1.z += a1.z * a1.z; q1.w += a1.w * a1.w;
    }
    atomicAdd(&ssum[lane * 4 + 0], s0.x); atomicAdd(&ssum[lane * 4 + 1], s0.y);
    atomicAdd(&ssum[lane * 4 + 2], s0.z); atomicAdd(&ssum[lane * 4 + 3], s0.w);
    atomicAdd(&ssum[128 + lane * 4 + 0], s1.x); atomicAdd(&ssum[128 + lane * 4 + 1], s1.y);
    atomicAdd(&ssum[128 + lane * 4 + 2], s1.z); atomicAdd(&ssum[128 + lane * 4 + 3], s1.w);
    atomicAdd(&ssq[lane * 4 + 0], q0.x); atomicAdd(&ssq[lane * 4 + 1], q0.y);
    atomicAdd(&ssq[lane * 4 + 2], q0.z); atomicAdd(&ssq[lane * 4 + 3], q0.w);
    atomicAdd(&ssq[128 + lane * 4 + 0], q1.x); atomicAdd(&ssq[128 + lane * 4 + 1], q1.y);
    atomicAdd(&ssq[128 + lane * 4 + 2], q1.z); atomicAdd(&ssq[128 + lane * 4 + 3], q1.w);
    __syncthreads();
    atomicAdd(&g_csum[tid], ssum[tid]);
    atomicAdd(&g_csq[tid], ssq[tid]);
}

// ---------------- batchnorm + relu (in-place on out) ----------------
__global__ void k_bn(float* __restrict__ out, const float* __restrict__ gamma,
                     const float* __restrict__ beta, int M) {
    int i = blockIdx.x * blockDim.x + threadIdx.x;
    if (i >= M * FO) return;
    int c = i & (FO - 1);
    float inv = 1.0f / (float)M;
    float mean = g_csum[c] * inv;
    float var = g_csq[c] * inv - mean * mean;
    float v = out[i];
    float y = gamma[c] * (v - mean) * (1.0f / sqrtf(var + 1e-5f)) + beta[c];
    out[i] = fmaxf(y, 0.f);
}

// ---------------- copy receptive_field into output (as float) ----------------
__global__ void k_rfcopy(const int* __restrict__ rf, float* __restrict__ out, int cnt) {
    int i = blockIdx.x * blockDim.x + threadIdx.x;
    if (i < cnt) out[i] = (float)rf[i];
}

// ---------------- stage 2: 32-way merge of pre-sorted adj rows, top-32 ----------------
__global__ __launch_bounds__(256) void k_stage2(const int* __restrict__ rf,
                                                float* __restrict__ out, int M) {
    int lane = threadIdx.x & 31;
    int gw = (blockIdx.x * blockDim.x + threadIdx.x) >> 5;
    if (gw >= M) return;
    int rfl = rf[gw * RD + lane];
    unsigned key[32];
    unsigned idv[32];
#pragma unroll
    for (int c = 0; c < 32; c++) {
        int v = __shfl_sync(FULLM, rfl, c);
        uint2 pr = g_sorted[v * RD + lane];
        key[c] = pr.x;
        idv[c] = pr.y;
    }
#pragma unroll
    for (int st = 1; st < 32; st <<= 1) {
#pragma unroll
        for (int c = 0; c < 32; c += (st << 1)) {
            unsigned bk = __shfl_sync(FULLM, key[c + st], 31 - lane);
            unsigned bi = __shfl_sync(FULLM, idv[c + st], 31 - lane);
            if (bk > key[c]) { key[c] = bk; idv[c] = bi; }
#pragma unroll
            for (int s = 16; s >= 1; s >>= 1) {
                unsigned ok = __shfl_xor_sync(FULLM, key[c], s);
                unsigned oi = __shfl_xor_sync(FULLM, idv[c], s);
                bool lower = (lane & s) == 0;
                bool take = lower ? (ok > key[c]) : (ok < key[c]);
                if (take) { key[c] = ok; idv[c] = oi; }
            }
        }
    }
    out[gw * RD + lane] = (float)idv[0];
}

// ---------------- launch (with capture-safe stream forks) ----------------
extern "C" void kernel_launch(void* const* d_in, const int* in_sizes, int n_in,
                              void* d_out, int out_size) {
    const float* x = (const float*)d_in[0];
    const int* rf = (const int*)d_in[1];
    const int* adj = (const int*)d_in[2];
    const float* W = (const float*)d_in[3];
    const float* B = (const float*)d_in[4];
    const float* Wk = (const float*)d_in[5];
    const float* Bk = (const float*)d_in[6];
    const float* Wq = (const float*)d_in[7];
    const float* Bq = (const float*)d_in[8];
    const float* la = (const float*)d_in[9];
    const float* ra = (const float*)d_in[10];
    const float* Bla = (const float*)d_in[11];
    const float* Bra = (const float*)d_in[12];
    const float* gamma = (const float*)d_in[13];
    const float* beta = (const float*)d_in[14];
    float* out = (float*)d_out;
    int M = in_sizes[0] / FI;

    static cudaStream_t s1 = 0, s2 = 0;
    static cudaEvent_t e0 = 0, e1 = 0, e2 = 0, e3 = 0;
    if (!s1) {
        cudaStreamCreateWithFlags(&s1, cudaStreamNonBlocking);
        cudaStreamCreateWithFlags(&s2, cudaStreamNonBlocking);
        cudaEventCreateWithFlags(&e0, cudaEventDisableTiming);
        cudaEventCreateWithFlags(&e1, cudaEventDisableTiming);
        cudaEventCreateWithFlags(&e2, cudaEventDisableTiming);
        cudaEventCreateWithFlags(&e3, cudaEventDisableTiming);
    }
    bool tail = (out_size >= M * FO + 2 * M * RD);

    k_zero<<<1, 256>>>();

    // fork: k_kq runs on s1 concurrent with k_gemm
    cudaEventRecord(e0, 0);
    cudaStreamWaitEvent(s1, e0, 0);
    k_kq<<<(M + 7) / 8, 128, 0, s1>>>(x, Wk, Bk, Wq, Bq, M);
    cudaEventRecord(e1, s1);

    dim3 gg(FO / TN, (M + TM - 1) / TM);
    k_gemm<<<gg, 256>>>(x, W, B, M);
    k_lars<<<(M + 7) / 8, 256>>>(la, ra, Bla, Bra, M);
    k_sortadj<<<(M + 7) / 8, 256>>>(adj, M);

    if (tail) {
        // fork: rfcopy + stage2 run on s2 concurrent with stage1 (disjoint out ranges)
        cudaEventRecord(e2, 0);
        cudaStreamWaitEvent(s2, e2, 0);
        k_rfcopy<<<(M * RD + 255) / 256, 256, 0, s2>>>(rf, out + M * FO, M * RD);
        k_stage2<<<(M + 7) / 8, 256, 0, s2>>>(rf, out + M * FO + M * RD, M);
        cudaEventRecord(e3, s2);
    }

    cudaStreamWaitEvent(0, e1, 0);   // stage1 needs Key/Query
    int blocks1 = 296;
    k_stage1<<<blocks1, 256>>>(rf, out, M, blocks1 * 8);
    k_bn<<<(M * FO + 255) / 256, 256>>>(out, gamma, beta, M);

    if (tail) cudaStreamWaitEvent(0, e3, 0);   // join before capture ends
}